// round 2
// baseline (speedup 1.0000x reference)
#include <cuda_runtime.h>
#include <cuda_bf16.h>
#include <math.h>

// Problem constants
#define BB   32
#define SS   96
#define TT   96
#define EE   256
#define HH   512
#define H4   2048
#define VV   32000
#define BH   (BB*HH)            // 16384

// ---------------------------------------------------------------------------
// Scratch (device globals; no allocations allowed)
// ---------------------------------------------------------------------------
__device__ float g_x0 [BB*SS*EE];        // embedded src / trg (reused)
__device__ float g_xpA[BB*SS*H4];        // input-projected gates, dir A
__device__ float g_xpB[BB*SS*H4];        // input-projected gates, dir B
__device__ float g_x1 [BB*SS*2*HH];      // encoder L0 output (concat f/b)
__device__ float g_x2 [BB*SS*2*HH];      // encoder L1 output (concat f/b)
__device__ float g_enc[BB*SS*HH];        // enc_out [B,S,H]
__device__ float g_dh0[BB*TT*HH];        // decoder L0 hidden seq
__device__ float g_comb[BB*TT*2*HH];     // [y | context]  -> FC input
__device__ float g_hbuf[6*2*BH];         // h state, 6 dirs x ping-pong
__device__ float g_cbuf[6*BH];           // c state, 6 dirs
__device__ float g_cat [4*BB*2*HH];      // concat hT/cT for bridge projections

// ---------------------------------------------------------------------------
// Embedding lookup: out[i, 0:256] = emb[idx[i], 0:256]
// ---------------------------------------------------------------------------
__global__ void embed_kernel(const int* __restrict__ idx,
                             const float* __restrict__ emb,
                             float* __restrict__ out)
{
    int i = blockIdx.x;          // token index (B*S)
    int e = threadIdx.x;         // 0..255
    out[(size_t)i * EE + e] = emb[(size_t)idx[i] * EE + e];
}

// ---------------------------------------------------------------------------
// Generic fp32 GEMM: C[M,N] = A[M,K] * W[N,K]^T + bias[N]
// Both A and W are K-contiguous (row-major). Requires M%128==0, N%128==0, K%8==0.
// 128x128 block tile, BK=8, 8x8 per-thread tile, 256 threads.
// ---------------------------------------------------------------------------
__global__ __launch_bounds__(256)
void sgemm_nt_bias(const float* __restrict__ A, const float* __restrict__ W,
                   const float* __restrict__ bias, float* __restrict__ C,
                   int M, int N, int K)
{
    __shared__ float As[8][128];
    __shared__ float Ws[8][128];

    const int tid = threadIdx.x;
    const int bn  = blockIdx.x;
    const int bm  = blockIdx.y;

    const float* Ab = A + (size_t)bm * 128 * K;
    const float* Wb = W + (size_t)bn * 128 * K;

    const int lrow = tid >> 1;           // 0..127
    const int lcol = (tid & 1) << 2;     // 0 or 4

    const int tx = tid & 15;             // N dir
    const int ty = tid >> 4;             // M dir

    float acc[8][8];
#pragma unroll
    for (int i = 0; i < 8; i++)
#pragma unroll
        for (int j = 0; j < 8; j++) acc[i][j] = 0.f;

    for (int k0 = 0; k0 < K; k0 += 8) {
        float4 a4 = *(const float4*)(Ab + (size_t)lrow * K + k0 + lcol);
        float4 w4 = *(const float4*)(Wb + (size_t)lrow * K + k0 + lcol);
        As[lcol+0][lrow] = a4.x; As[lcol+1][lrow] = a4.y;
        As[lcol+2][lrow] = a4.z; As[lcol+3][lrow] = a4.w;
        Ws[lcol+0][lrow] = w4.x; Ws[lcol+1][lrow] = w4.y;
        Ws[lcol+2][lrow] = w4.z; Ws[lcol+3][lrow] = w4.w;
        __syncthreads();

#pragma unroll
        for (int kk = 0; kk < 8; kk++) {
            float4 a0 = *(const float4*)&As[kk][ty*8];
            float4 a1 = *(const float4*)&As[kk][ty*8+4];
            float4 w0 = *(const float4*)&Ws[kk][tx*8];
            float4 w1 = *(const float4*)&Ws[kk][tx*8+4];
            float ar[8] = {a0.x,a0.y,a0.z,a0.w,a1.x,a1.y,a1.z,a1.w};
            float wr[8] = {w0.x,w0.y,w0.z,w0.w,w1.x,w1.y,w1.z,w1.w};
#pragma unroll
            for (int i = 0; i < 8; i++)
#pragma unroll
                for (int j = 0; j < 8; j++)
                    acc[i][j] = fmaf(ar[i], wr[j], acc[i][j]);
        }
        __syncthreads();
    }

    const int m0 = bm * 128 + ty * 8;
    const int n0 = bn * 128 + tx * 8;
#pragma unroll
    for (int i = 0; i < 8; i++) {
#pragma unroll
        for (int j = 0; j < 8; j += 4) {
            float4 o;
            o.x = acc[i][j+0] + bias[n0+j+0];
            o.y = acc[i][j+1] + bias[n0+j+1];
            o.z = acc[i][j+2] + bias[n0+j+2];
            o.w = acc[i][j+3] + bias[n0+j+3];
            *(float4*)(C + (size_t)(m0+i) * N + n0 + j) = o;
        }
    }
}

// ---------------------------------------------------------------------------
// LSTM step. Each launch advances one timestep of up to two directions.
// Block: 256 threads = (b 0..31) x (rl 0..7); each thread owns cell j for all
// 4 gates. grid.x = 64 (j chunks of 8), grid.z = ndir.
// Dynamic smem: h_prev transposed [k][b] = 64 KB.
// ---------------------------------------------------------------------------
struct LstmDirParams {
    const float* __restrict__ xp;    // [B*S, 2048] rows = b*96+t
    const float* __restrict__ Whh;   // [2048, 512]
    const float* __restrict__ h_in;  // [B,512]
    float* __restrict__ h_out;       // [B,512]
    float* __restrict__ c;           // [B,512] in-place
    float* __restrict__ out;         // hidden-seq output base
    int out_stride;                  // row stride (512 or 1024)
    int out_col;                     // column offset (0 or 512)
    int t;                           // actual time index (read & write)
};

__device__ __forceinline__ float sigf(float x) { return 1.f / (1.f + expf(-x)); }

__global__ __launch_bounds__(256)
void lstm_step_kernel(LstmDirParams p0, LstmDirParams p1)
{
    const LstmDirParams p = (blockIdx.z == 0) ? p0 : p1;

    extern __shared__ float hs[];         // [512][32] -> hs[k*32 + b]
    const int tid  = threadIdx.x;
    const int lane = tid & 31;
    const int w    = tid >> 5;            // warp id 0..7

    // Stage h_in transposed: warp w covers k in [w*64, w*64+64); lane = batch.
    {
        const float* hrow = p.h_in + (size_t)lane * HH + w * 64;
#pragma unroll
        for (int kk = 0; kk < 16; kk++) {
            float4 v = *(const float4*)(hrow + kk * 4);
            int k = w * 64 + kk * 4;
            hs[(k+0)*32 + lane] = v.x;
            hs[(k+1)*32 + lane] = v.y;
            hs[(k+2)*32 + lane] = v.z;
            hs[(k+3)*32 + lane] = v.w;
        }
    }

    const int b  = lane;
    const int j  = blockIdx.x * 8 + w;    // cell index 0..511

    // Hoist xp gate pre-activations (independent loads, overlap with barrier)
    const size_t xoff = ((size_t)b * SS + p.t) * (size_t)H4;
    const float xi = p.xp[xoff + 0*HH + j];
    const float xf = p.xp[xoff + 1*HH + j];
    const float xg = p.xp[xoff + 2*HH + j];
    const float xo = p.xp[xoff + 3*HH + j];

    const float4* __restrict__ wi4 = (const float4*)(p.Whh + (size_t)(0*HH + j) * HH);
    const float4* __restrict__ wf4 = (const float4*)(p.Whh + (size_t)(1*HH + j) * HH);
    const float4* __restrict__ wg4 = (const float4*)(p.Whh + (size_t)(2*HH + j) * HH);
    const float4* __restrict__ wo4 = (const float4*)(p.Whh + (size_t)(3*HH + j) * HH);

    __syncthreads();

    float ai = 0.f, af = 0.f, ag = 0.f, ao = 0.f;
#pragma unroll 4
    for (int k4 = 0; k4 < HH/4; k4++) {
        float h0v = hs[(k4*4+0)*32 + b];
        float h1v = hs[(k4*4+1)*32 + b];
        float h2v = hs[(k4*4+2)*32 + b];
        float h3v = hs[(k4*4+3)*32 + b];
        float4 vi = wi4[k4], vf = wf4[k4], vg = wg4[k4], vo = wo4[k4];
        ai = fmaf(h0v, vi.x, fmaf(h1v, vi.y, fmaf(h2v, vi.z, fmaf(h3v, vi.w, ai))));
        af = fmaf(h0v, vf.x, fmaf(h1v, vf.y, fmaf(h2v, vf.z, fmaf(h3v, vf.w, af))));
        ag = fmaf(h0v, vg.x, fmaf(h1v, vg.y, fmaf(h2v, vg.z, fmaf(h3v, vg.w, ag))));
        ao = fmaf(h0v, vo.x, fmaf(h1v, vo.y, fmaf(h2v, vo.z, fmaf(h3v, vo.w, ao))));
    }

    const float ig = sigf(ai + xi);
    const float fg = sigf(af + xf);
    const float gg = tanhf(ag + xg);
    const float og = sigf(ao + xo);

    const int sidx = b * HH + j;
    const float cnew = fg * p.c[sidx] + ig * gg;
    const float hnew = og * tanhf(cnew);

    p.c[sidx]     = cnew;
    p.h_out[sidx] = hnew;
    p.out[((size_t)b * SS + p.t) * (size_t)p.out_stride + p.out_col + j] = hnew;
}

// ---------------------------------------------------------------------------
// Build concatenated final states for bridge projections.
// g_cat layout: [which][B][1024], which = 0:h_l0, 1:c_l0, 2:h_l1, 3:c_l1
// Final h lives in ping buffer 0 (96 steps, even).
// ---------------------------------------------------------------------------
__global__ void cat_states_kernel()
{
    int i = blockIdx.x * 256 + threadIdx.x;     // over 4*32*1024
    if (i >= 4 * BB * 2 * HH) return;
    int col   = i & 1023;
    int b     = (i >> 10) & 31;
    int which = i >> 15;
    int layer = which >> 1;
    bool is_c = which & 1;
    int dir   = layer * 2 + ((col < HH) ? 0 : 1);
    int j     = col & (HH - 1);
    float v;
    if (is_c) v = g_cbuf[(size_t)dir * BH + b * HH + j];
    else      v = g_hbuf[(size_t)(dir * 2 + 0) * BH + b * HH + j];
    g_cat[i] = v;
}

// ---------------------------------------------------------------------------
// Small projection: C[32,512] = A[32,1024] @ W[512,1024]^T + bias
// ---------------------------------------------------------------------------
__global__ __launch_bounds__(256)
void proj_kernel(const float* __restrict__ A, const float* __restrict__ W,
                 const float* __restrict__ bias, float* __restrict__ C)
{
    int gid = blockIdx.x * 256 + threadIdx.x;   // 64 blocks -> 16384 outputs
    int b = gid >> 9;
    int n = gid & 511;
    const float4* a4 = (const float4*)(A + (size_t)b * 1024);
    const float4* w4 = (const float4*)(W + (size_t)n * 1024);
    float acc = 0.f;
#pragma unroll 4
    for (int k = 0; k < 256; k++) {
        float4 a = a4[k], w = w4[k];
        acc = fmaf(a.x, w.x, fmaf(a.y, w.y, fmaf(a.z, w.z, fmaf(a.w, w.w, acc))));
    }
    C[b * HH + n] = acc + bias[n];
}

// ---------------------------------------------------------------------------
// Attention per (b,t): energy over s, PAD mask, softmax, context.
// y is already in g_comb[bt, 0:512]; context written to g_comb[bt, 512:1024].
// ---------------------------------------------------------------------------
__global__ __launch_bounds__(128)
void attn_kernel(const int* __restrict__ src_seq)
{
    const int bt = blockIdx.x;
    const int b  = bt / TT;
    const int tid = threadIdx.x;

    __shared__ float yrow[HH];
    __shared__ float prob[SS];
    __shared__ float rbuf[128];

    const float* ybase = g_comb + (size_t)bt * (2*HH);
    for (int d = tid; d < HH; d += 128) yrow[d] = ybase[d];
    __syncthreads();

    // energies (thread-per-s)
    for (int s = tid; s < SS; s += 128) {
        const float4* er = (const float4*)(g_enc + ((size_t)b * SS + s) * HH);
        const float4* y4 = (const float4*)yrow;
        float acc = 0.f;
#pragma unroll 4
        for (int k = 0; k < HH/4; k++) {
            float4 e = er[k], y = y4[k];
            acc = fmaf(e.x, y.x, fmaf(e.y, y.y, fmaf(e.z, y.z, fmaf(e.w, y.w, acc))));
        }
        if (src_seq[b * SS + s] == 0) acc = -1e10f;
        prob[s] = acc;
    }
    __syncthreads();

    // max reduce
    float m = -3.0e38f;
    for (int s = tid; s < SS; s += 128) m = fmaxf(m, prob[s]);
    rbuf[tid] = m; __syncthreads();
    for (int off = 64; off > 0; off >>= 1) {
        if (tid < off) rbuf[tid] = fmaxf(rbuf[tid], rbuf[tid + off]);
        __syncthreads();
    }
    m = rbuf[0]; __syncthreads();

    // exp + sum reduce
    float ssum = 0.f;
    for (int s = tid; s < SS; s += 128) {
        float pv = expf(prob[s] - m);
        prob[s] = pv;
        ssum += pv;
    }
    rbuf[tid] = ssum; __syncthreads();
    for (int off = 64; off > 0; off >>= 1) {
        if (tid < off) rbuf[tid] += rbuf[tid + off];
        __syncthreads();
    }
    const float inv = 1.f / rbuf[0];
    __syncthreads();

    // context (thread-per-d, coalesced)
    for (int d = tid; d < HH; d += 128) {
        float acc = 0.f;
#pragma unroll 8
        for (int s = 0; s < SS; s++)
            acc = fmaf(prob[s], g_enc[((size_t)b * SS + s) * HH + d], acc);
        g_comb[(size_t)bt * (2*HH) + HH + d] = acc * inv;
    }
}

// ---------------------------------------------------------------------------
// Host orchestration
// ---------------------------------------------------------------------------
extern "C" void kernel_launch(void* const* d_in, const int* in_sizes, int n_in,
                              void* d_out, int out_size)
{
    const int*   src_seq = (const int*)  d_in[0];
    const int*   trg_seq = (const int*)  d_in[1];
    const float* src_emb = (const float*)d_in[2];
    const float* trg_emb = (const float*)d_in[3];
    const float* eW0f = (const float*)d_in[4];
    const float* eU0f = (const float*)d_in[5];
    const float* eb0f = (const float*)d_in[6];
    const float* eW0b = (const float*)d_in[7];
    const float* eU0b = (const float*)d_in[8];
    const float* eb0b = (const float*)d_in[9];
    const float* eW1f = (const float*)d_in[10];
    const float* eU1f = (const float*)d_in[11];
    const float* eb1f = (const float*)d_in[12];
    const float* eW1b = (const float*)d_in[13];
    const float* eU1b = (const float*)d_in[14];
    const float* eb1b = (const float*)d_in[15];
    const float* out_W = (const float*)d_in[16];
    const float* out_b = (const float*)d_in[17];
    const float* hpW  = (const float*)d_in[18];
    const float* hpb  = (const float*)d_in[19];
    const float* cpW  = (const float*)d_in[20];
    const float* cpb  = (const float*)d_in[21];
    const float* dW0  = (const float*)d_in[22];
    const float* dU0  = (const float*)d_in[23];
    const float* db0  = (const float*)d_in[24];
    const float* dW1  = (const float*)d_in[25];
    const float* dU1  = (const float*)d_in[26];
    const float* db1  = (const float*)d_in[27];
    const float* fcW  = (const float*)d_in[28];
    const float* fcb  = (const float*)d_in[29];
    float* out = (float*)d_out;

    float *x0, *xpA, *xpB, *x1, *x2, *enc, *dh0, *comb, *hbuf, *cbuf, *cat;
    cudaGetSymbolAddress((void**)&x0,   g_x0);
    cudaGetSymbolAddress((void**)&xpA,  g_xpA);
    cudaGetSymbolAddress((void**)&xpB,  g_xpB);
    cudaGetSymbolAddress((void**)&x1,   g_x1);
    cudaGetSymbolAddress((void**)&x2,   g_x2);
    cudaGetSymbolAddress((void**)&enc,  g_enc);
    cudaGetSymbolAddress((void**)&dh0,  g_dh0);
    cudaGetSymbolAddress((void**)&comb, g_comb);
    cudaGetSymbolAddress((void**)&hbuf, g_hbuf);
    cudaGetSymbolAddress((void**)&cbuf, g_cbuf);
    cudaGetSymbolAddress((void**)&cat,  g_cat);

    cudaFuncSetAttribute(lstm_step_kernel,
                         cudaFuncAttributeMaxDynamicSharedMemorySize, 65536);

    // zero encoder initial states (dirs 0..3, both ping buffers + c)
    cudaMemsetAsync(hbuf, 0, (size_t)4 * 2 * BH * sizeof(float));
    cudaMemsetAsync(cbuf, 0, (size_t)4 * BH * sizeof(float));

    const int M = BB * SS;                      // 3072
    const dim3 gN2048(H4/128, M/128);           // (16, 24)
    const dim3 gN512 (HH/128, M/128);           // (4, 24)

    // ---- encoder ----
    embed_kernel<<<M, EE>>>(src_seq, src_emb, x0);
    sgemm_nt_bias<<<gN2048, 256>>>(x0, eW0f, eb0f, xpA, M, H4, EE);
    sgemm_nt_bias<<<gN2048, 256>>>(x0, eW0b, eb0b, xpB, M, H4, EE);

    for (int t = 0; t < SS; t++) {
        LstmDirParams pf = { xpA, eU0f,
                             hbuf + (size_t)(0*2 + (t&1))*BH, hbuf + (size_t)(0*2 + ((t+1)&1))*BH,
                             cbuf + (size_t)0*BH, x1, 2*HH, 0, t };
        LstmDirParams pb = { xpB, eU0b,
                             hbuf + (size_t)(1*2 + (t&1))*BH, hbuf + (size_t)(1*2 + ((t+1)&1))*BH,
                             cbuf + (size_t)1*BH, x1, 2*HH, HH, SS-1-t };
        lstm_step_kernel<<<dim3(64,1,2), 256, 65536>>>(pf, pb);
    }

    sgemm_nt_bias<<<gN2048, 256>>>(x1, eW1f, eb1f, xpA, M, H4, 2*HH);
    sgemm_nt_bias<<<gN2048, 256>>>(x1, eW1b, eb1b, xpB, M, H4, 2*HH);

    for (int t = 0; t < SS; t++) {
        LstmDirParams pf = { xpA, eU1f,
                             hbuf + (size_t)(2*2 + (t&1))*BH, hbuf + (size_t)(2*2 + ((t+1)&1))*BH,
                             cbuf + (size_t)2*BH, x2, 2*HH, 0, t };
        LstmDirParams pb = { xpB, eU1b,
                             hbuf + (size_t)(3*2 + (t&1))*BH, hbuf + (size_t)(3*2 + ((t+1)&1))*BH,
                             cbuf + (size_t)3*BH, x2, 2*HH, HH, SS-1-t };
        lstm_step_kernel<<<dim3(64,1,2), 256, 65536>>>(pf, pb);
    }

    sgemm_nt_bias<<<gN512, 256>>>(x2, out_W, out_b, enc, M, HH, 2*HH);

    // ---- bridge: concat final states, project into decoder initial states ----
    cat_states_kernel<<<(4*BB*2*HH + 255)/256, 256>>>();
    proj_kernel<<<64, 256>>>(cat + 0*BB*2*HH, hpW,                hpb,       hbuf + (size_t)(4*2+0)*BH);
    proj_kernel<<<64, 256>>>(cat + 1*BB*2*HH, cpW,                cpb,       cbuf + (size_t)4*BH);
    proj_kernel<<<64, 256>>>(cat + 2*BB*2*HH, hpW + (size_t)HH*2*HH, hpb + HH, hbuf + (size_t)(5*2+0)*BH);
    proj_kernel<<<64, 256>>>(cat + 3*BB*2*HH, cpW + (size_t)HH*2*HH, cpb + HH, cbuf + (size_t)5*BH);

    // ---- decoder layer 0 ----
    embed_kernel<<<M, EE>>>(trg_seq, trg_emb, x0);
    sgemm_nt_bias<<<gN2048, 256>>>(x0, dW0, db0, xpA, M, H4, EE);
    for (int t = 0; t < TT; t++) {
        LstmDirParams p = { xpA, dU0,
                            hbuf + (size_t)(4*2 + (t&1))*BH, hbuf + (size_t)(4*2 + ((t+1)&1))*BH,
                            cbuf + (size_t)4*BH, dh0, HH, 0, t };
        lstm_step_kernel<<<dim3(64,1,1), 256, 65536>>>(p, p);
    }

    // ---- decoder layer 1 (writes y into combined[:, 0:512]) ----
    sgemm_nt_bias<<<gN2048, 256>>>(dh0, dW1, db1, xpA, M, H4, HH);
    for (int t = 0; t < TT; t++) {
        LstmDirParams p = { xpA, dU1,
                            hbuf + (size_t)(5*2 + (t&1))*BH, hbuf + (size_t)(5*2 + ((t+1)&1))*BH,
                            cbuf + (size_t)5*BH, comb, 2*HH, 0, t };
        lstm_step_kernel<<<dim3(64,1,1), 256, 65536>>>(p, p);
    }

    // ---- attention (fills combined[:, 512:1024]) ----
    attn_kernel<<<M, 128>>>(src_seq);

    // ---- final FC: [3072,1024] x [1024,32000]^T + fcb ----
    sgemm_nt_bias<<<dim3(VV/128, M/128), 256>>>(comb, fcW, fcb, out, M, VV, 2*HH);
}

// round 5
// speedup vs baseline: 1.4589x; 1.4589x over previous
#include <cuda_runtime.h>
#include <cuda_bf16.h>
#include <math.h>

// Problem constants
#define BB   32
#define SS   96
#define TT   96
#define EE   256
#define HH   512
#define H4   2048
#define VV   32000
#define BH   (BB*HH)            // 16384

// ---------------------------------------------------------------------------
// Scratch (device globals; no allocations allowed)
// ---------------------------------------------------------------------------
__device__ float g_x0 [BB*SS*EE];        // embedded src / trg (reused)
__device__ float g_xpA[BB*SS*H4];        // input-projected gates, dir A
__device__ float g_xpB[BB*SS*H4];        // input-projected gates, dir B
__device__ float g_x1 [BB*SS*2*HH];      // encoder L0 output (concat f/b)
__device__ float g_x2 [BB*SS*2*HH];      // encoder L1 output (concat f/b)
__device__ float g_enc[BB*SS*HH];        // enc_out [B,S,H]
__device__ float g_dh0[BB*TT*HH];        // decoder L0 hidden seq
__device__ float g_comb[BB*TT*2*HH];     // [y | context]  -> FC input
__device__ float g_hbuf[6*2*BH];         // h state, 6 dirs x ping-pong
__device__ float g_cbuf[6*BH];           // c state, 6 dirs
__device__ float g_cat [4*BB*2*HH];      // concat hT/cT for bridge projections

// Grid-wide software barrier state (self-resetting)
__device__ unsigned g_bar_cnt = 0;
__device__ unsigned g_bar_gen = 0;

// ---------------------------------------------------------------------------
// Embedding lookup: out[i, 0:256] = emb[idx[i], 0:256]
// ---------------------------------------------------------------------------
__global__ void embed_kernel(const int* __restrict__ idx,
                             const float* __restrict__ emb,
                             float* __restrict__ out)
{
    int i = blockIdx.x;          // token index (B*S)
    int e = threadIdx.x;         // 0..255
    out[(size_t)i * EE + e] = emb[(size_t)idx[i] * EE + e];
}

// ---------------------------------------------------------------------------
// Generic fp32 GEMM: C[M,N] = A[M,K] * W[N,K]^T + bias[N]
// ---------------------------------------------------------------------------
__global__ __launch_bounds__(256)
void sgemm_nt_bias(const float* __restrict__ A, const float* __restrict__ W,
                   const float* __restrict__ bias, float* __restrict__ C,
                   int M, int N, int K)
{
    __shared__ float As[8][128];
    __shared__ float Ws[8][128];

    const int tid = threadIdx.x;
    const int bn  = blockIdx.x;
    const int bm  = blockIdx.y;

    const float* Ab = A + (size_t)bm * 128 * K;
    const float* Wb = W + (size_t)bn * 128 * K;

    const int lrow = tid >> 1;           // 0..127
    const int lcol = (tid & 1) << 2;     // 0 or 4

    const int tx = tid & 15;             // N dir
    const int ty = tid >> 4;             // M dir

    float acc[8][8];
#pragma unroll
    for (int i = 0; i < 8; i++)
#pragma unroll
        for (int j = 0; j < 8; j++) acc[i][j] = 0.f;

    for (int k0 = 0; k0 < K; k0 += 8) {
        float4 a4 = *(const float4*)(Ab + (size_t)lrow * K + k0 + lcol);
        float4 w4 = *(const float4*)(Wb + (size_t)lrow * K + k0 + lcol);
        As[lcol+0][lrow] = a4.x; As[lcol+1][lrow] = a4.y;
        As[lcol+2][lrow] = a4.z; As[lcol+3][lrow] = a4.w;
        Ws[lcol+0][lrow] = w4.x; Ws[lcol+1][lrow] = w4.y;
        Ws[lcol+2][lrow] = w4.z; Ws[lcol+3][lrow] = w4.w;
        __syncthreads();

#pragma unroll
        for (int kk = 0; kk < 8; kk++) {
            float4 a0 = *(const float4*)&As[kk][ty*8];
            float4 a1 = *(const float4*)&As[kk][ty*8+4];
            float4 w0 = *(const float4*)&Ws[kk][tx*8];
            float4 w1 = *(const float4*)&Ws[kk][tx*8+4];
            float ar[8] = {a0.x,a0.y,a0.z,a0.w,a1.x,a1.y,a1.z,a1.w};
            float wr[8] = {w0.x,w0.y,w0.z,w0.w,w1.x,w1.y,w1.z,w1.w};
#pragma unroll
            for (int i = 0; i < 8; i++)
#pragma unroll
                for (int j = 0; j < 8; j++)
                    acc[i][j] = fmaf(ar[i], wr[j], acc[i][j]);
        }
        __syncthreads();
    }

    const int m0 = bm * 128 + ty * 8;
    const int n0 = bn * 128 + tx * 8;
#pragma unroll
    for (int i = 0; i < 8; i++) {
#pragma unroll
        for (int j = 0; j < 8; j += 4) {
            float4 o;
            o.x = acc[i][j+0] + bias[n0+j+0];
            o.y = acc[i][j+1] + bias[n0+j+1];
            o.z = acc[i][j+2] + bias[n0+j+2];
            o.w = acc[i][j+3] + bias[n0+j+3];
            *(float4*)(C + (size_t)(m0+i) * N + n0 + j) = o;
        }
    }
}

// ---------------------------------------------------------------------------
// Persistent LSTM recurrence.
// One launch runs all timesteps of 1-2 directions. Whh slice lives in SMEM
// for the whole sequence; h ping-pongs through global (L2-coherent
// __ldcg/__stcg); c stays in a register. Grid-wide software barrier between
// steps (128 blocks, 131072 B smem => exactly 1 block/SM, single wave).
// NJPB = cells per block (8 -> no k-split, 4 -> 2-way k-split w/ smem reduce)
// ---------------------------------------------------------------------------
struct PDir {
    const float* xp;     // [B*S, 2048]
    const float* Whh;    // [2048, 512]
    float* hping;        // 2*BH floats: ping-pong h state
    float* c;            // [B,512] initial/final c
    float* out;          // hidden-seq output base
    int out_stride;      // 512 or 1024
    int out_col;         // 0 or 512
    int reverse;         // bwd direction?
};

__device__ __forceinline__ float sigf(float x) { return 1.f / (1.f + expf(-x)); }

__device__ __forceinline__ void grid_barrier(unsigned nblocks)
{
    __threadfence();
    __syncthreads();
    if (threadIdx.x == 0) {
        unsigned gen = *((volatile unsigned*)&g_bar_gen);
        unsigned ticket = atomicAdd(&g_bar_cnt, 1);
        if (ticket == nblocks - 1) {
            g_bar_cnt = 0;
            __threadfence();
            *((volatile unsigned*)&g_bar_gen) = gen + 1;
        } else {
            while (*((volatile unsigned*)&g_bar_gen) == gen) __nanosleep(40);
        }
    }
    __syncthreads();
    __threadfence();
}

template<int NJPB, int NDIR>
__global__ __launch_bounds__(256)
void lstm_persist_kernel(PDir d0, PDir d1, int nsteps, unsigned nblocks)
{
    constexpr int BPD = HH / NJPB;          // blocks per direction
    constexpr int KS  = 8 / NJPB;           // k-split factor (1 or 2)

    const PDir p   = (NDIR == 2 && blockIdx.x >= BPD) ? d1 : d0;
    const int chunk = (NDIR == 2) ? (blockIdx.x % BPD) : blockIdx.x;

    extern __shared__ float sm[];
    float* hs  = sm;                        // [128][32][4]  (k4-major h staging)
    float* ws  = sm + HH * BB;              // [4*NJPB][512] weights
    float* red = ws + 4 * NJPB * HH;        // [4*NJPB][32]  (KS==2 only)

    const int tid   = threadIdx.x;
    const int lane  = tid & 31;             // batch b
    const int w     = tid >> 5;             // warp 0..7
    const int cell  = w % NJPB;
    const int khalf = w / NJPB;             // 0..KS-1
    const int j     = chunk * NJPB + cell;  // cell index 0..511
    const int b     = lane;

    // Load this block's Whh slice into smem (rows: gate-major, 512 each)
    for (int idx = tid; idx < 4 * NJPB * 128; idx += 256) {
        int srow  = idx >> 7;               // 0..4*NJPB-1
        int k4    = idx & 127;
        int gate  = srow / NJPB;
        int lcell = srow % NJPB;
        float4 v = *(const float4*)(p.Whh +
                     ((size_t)(gate * HH + chunk * NJPB + lcell)) * HH + k4 * 4);
        *(float4*)(ws + srow * HH + k4 * 4) = v;
    }

    float creg = p.c[b * HH + j];           // used by khalf==0 threads only

    const float4* wi4 = (const float4*)(ws + (0 * NJPB + cell) * HH);
    const float4* wf4 = (const float4*)(ws + (1 * NJPB + cell) * HH);
    const float4* wg4 = (const float4*)(ws + (2 * NJPB + cell) * HH);
    const float4* wo4 = (const float4*)(ws + (3 * NJPB + cell) * HH);

    const int k4beg = khalf * (128 / KS);
    const int k4end = k4beg + (128 / KS);

    __syncthreads();   // weights ready (also orders with first staging)

    for (int t = 0; t < nsteps; t++) {
        const int par = t & 1;
        const float* hin = p.hping + (size_t)par * BH;

        // Stage h transposed to k4-major: hs[(k4*32 + b)*4 + kk]
        {
            const float* hrow = hin + (size_t)lane * HH + w * 64;
#pragma unroll
            for (int kk = 0; kk < 16; kk++) {
                float4 v = __ldcg((const float4*)(hrow + kk * 4));
                int k4g = w * 16 + kk;
                *(float4*)(hs + (k4g * 32 + lane) * 4) = v;
            }
        }

        const int trow = p.reverse ? (nsteps - 1 - t) : t;

        float xi = 0.f, xf = 0.f, xg = 0.f, xo = 0.f;
        if (khalf == 0) {
            const size_t xoff = ((size_t)b * SS + trow) * (size_t)H4;
            xi = p.xp[xoff + 0 * HH + j];
            xf = p.xp[xoff + 1 * HH + j];
            xg = p.xp[xoff + 2 * HH + j];
            xo = p.xp[xoff + 3 * HH + j];
        }
        __syncthreads();

        float ai = 0.f, af = 0.f, ag = 0.f, ao = 0.f;
#pragma unroll 4
        for (int k4 = k4beg; k4 < k4end; k4++) {
            float4 hv = *(const float4*)(hs + (k4 * 32 + b) * 4);
            float4 vi = wi4[k4], vf = wf4[k4], vg = wg4[k4], vo = wo4[k4];
            ai = fmaf(hv.x, vi.x, fmaf(hv.y, vi.y, fmaf(hv.z, vi.z, fmaf(hv.w, vi.w, ai))));
            af = fmaf(hv.x, vf.x, fmaf(hv.y, vf.y, fmaf(hv.z, vf.z, fmaf(hv.w, vf.w, af))));
            ag = fmaf(hv.x, vg.x, fmaf(hv.y, vg.y, fmaf(hv.z, vg.z, fmaf(hv.w, vg.w, ag))));
            ao = fmaf(hv.x, vo.x, fmaf(hv.y, vo.y, fmaf(hv.z, vo.z, fmaf(hv.w, vo.w, ao))));
        }

        if (KS == 2) {
            if (khalf == 1) {
                red[(0 * NJPB + cell) * 32 + lane] = ai;
                red[(1 * NJPB + cell) * 32 + lane] = af;
                red[(2 * NJPB + cell) * 32 + lane] = ag;
                red[(3 * NJPB + cell) * 32 + lane] = ao;
            }
            __syncthreads();
            if (khalf == 0) {
                ai += red[(0 * NJPB + cell) * 32 + lane];
                af += red[(1 * NJPB + cell) * 32 + lane];
                ag += red[(2 * NJPB + cell) * 32 + lane];
                ao += red[(3 * NJPB + cell) * 32 + lane];
            }
        }

        if (khalf == 0) {
            const float ig = sigf(ai + xi);
            const float fg = sigf(af + xf);
            const float gg = tanhf(ag + xg);
            const float og = sigf(ao + xo);

            const float cnew = fg * creg + ig * gg;
            const float hnew = og * tanhf(cnew);
            creg = cnew;

            float* hout = p.hping + (size_t)(par ^ 1) * BH;
            __stcg(hout + b * HH + j, hnew);
            p.out[((size_t)b * SS + trow) * (size_t)p.out_stride + p.out_col + j] = hnew;
        }

        grid_barrier(nblocks);
    }

    if (khalf == 0) p.c[b * HH + j] = creg;   // final c (for bridge concat)
}

// ---------------------------------------------------------------------------
// Build concatenated final states for bridge projections.
// ---------------------------------------------------------------------------
__global__ void cat_states_kernel()
{
    int i = blockIdx.x * 256 + threadIdx.x;     // over 4*32*1024
    if (i >= 4 * BB * 2 * HH) return;
    int col   = i & 1023;
    int b     = (i >> 10) & 31;
    int which = i >> 15;
    int layer = which >> 1;
    bool is_c = which & 1;
    int dir   = layer * 2 + ((col < HH) ? 0 : 1);
    int j     = col & (HH - 1);
    float v;
    if (is_c) v = g_cbuf[(size_t)dir * BH + b * HH + j];
    else      v = g_hbuf[(size_t)(dir * 2 + 0) * BH + b * HH + j];
    g_cat[i] = v;
}

// ---------------------------------------------------------------------------
// Small projection: C[32,512] = A[32,1024] @ W[512,1024]^T + bias
// ---------------------------------------------------------------------------
__global__ __launch_bounds__(256)
void proj_kernel(const float* __restrict__ A, const float* __restrict__ W,
                 const float* __restrict__ bias, float* __restrict__ C)
{
    int gid = blockIdx.x * 256 + threadIdx.x;   // 64 blocks -> 16384 outputs
    int b = gid >> 9;
    int n = gid & 511;
    const float4* a4 = (const float4*)(A + (size_t)b * 1024);
    const float4* w4 = (const float4*)(W + (size_t)n * 1024);
    float acc = 0.f;
#pragma unroll 4
    for (int k = 0; k < 256; k++) {
        float4 a = a4[k], w = w4[k];
        acc = fmaf(a.x, w.x, fmaf(a.y, w.y, fmaf(a.z, w.z, fmaf(a.w, w.w, acc))));
    }
    C[b * HH + n] = acc + bias[n];
}

// ---------------------------------------------------------------------------
// Attention per (b,t): energy over s, PAD mask, softmax, context.
// ---------------------------------------------------------------------------
__global__ __launch_bounds__(128)
void attn_kernel(const int* __restrict__ src_seq)
{
    const int bt = blockIdx.x;
    const int b  = bt / TT;
    const int tid = threadIdx.x;

    __shared__ float yrow[HH];
    __shared__ float prob[SS];
    __shared__ float rbuf[128];

    const float* ybase = g_comb + (size_t)bt * (2*HH);
    for (int d = tid; d < HH; d += 128) yrow[d] = ybase[d];
    __syncthreads();

    for (int s = tid; s < SS; s += 128) {
        const float4* er = (const float4*)(g_enc + ((size_t)b * SS + s) * HH);
        const float4* y4 = (const float4*)yrow;
        float acc = 0.f;
#pragma unroll 4
        for (int k = 0; k < HH/4; k++) {
            float4 e = er[k], y = y4[k];
            acc = fmaf(e.x, y.x, fmaf(e.y, y.y, fmaf(e.z, y.z, fmaf(e.w, y.w, acc))));
        }
        if (src_seq[b * SS + s] == 0) acc = -1e10f;
        prob[s] = acc;
    }
    __syncthreads();

    float m = -3.0e38f;
    for (int s = tid; s < SS; s += 128) m = fmaxf(m, prob[s]);
    rbuf[tid] = m; __syncthreads();
    for (int off = 64; off > 0; off >>= 1) {
        if (tid < off) rbuf[tid] = fmaxf(rbuf[tid], rbuf[tid + off]);
        __syncthreads();
    }
    m = rbuf[0]; __syncthreads();

    float ssum = 0.f;
    for (int s = tid; s < SS; s += 128) {
        float pv = expf(prob[s] - m);
        prob[s] = pv;
        ssum += pv;
    }
    rbuf[tid] = ssum; __syncthreads();
    for (int off = 64; off > 0; off >>= 1) {
        if (tid < off) rbuf[tid] += rbuf[tid + off];
        __syncthreads();
    }
    const float inv = 1.f / rbuf[0];
    __syncthreads();

    for (int d = tid; d < HH; d += 128) {
        float acc = 0.f;
#pragma unroll 8
        for (int s = 0; s < SS; s++)
            acc = fmaf(prob[s], g_enc[((size_t)b * SS + s) * HH + d], acc);
        g_comb[(size_t)bt * (2*HH) + HH + d] = acc * inv;
    }
}

// ---------------------------------------------------------------------------
// Host orchestration
// ---------------------------------------------------------------------------
extern "C" void kernel_launch(void* const* d_in, const int* in_sizes, int n_in,
                              void* d_out, int out_size)
{
    const int*   src_seq = (const int*)  d_in[0];
    const int*   trg_seq = (const int*)  d_in[1];
    const float* src_emb = (const float*)d_in[2];
    const float* trg_emb = (const float*)d_in[3];
    const float* eW0f = (const float*)d_in[4];
    const float* eU0f = (const float*)d_in[5];
    const float* eb0f = (const float*)d_in[6];
    const float* eW0b = (const float*)d_in[7];
    const float* eU0b = (const float*)d_in[8];
    const float* eb0b = (const float*)d_in[9];
    const float* eW1f = (const float*)d_in[10];
    const float* eU1f = (const float*)d_in[11];
    const float* eb1f = (const float*)d_in[12];
    const float* eW1b = (const float*)d_in[13];
    const float* eU1b = (const float*)d_in[14];
    const float* eb1b = (const float*)d_in[15];
    const float* out_W = (const float*)d_in[16];
    const float* out_b = (const float*)d_in[17];
    const float* hpW  = (const float*)d_in[18];
    const float* hpb  = (const float*)d_in[19];
    const float* cpW  = (const float*)d_in[20];
    const float* cpb  = (const float*)d_in[21];
    const float* dW0  = (const float*)d_in[22];
    const float* dU0  = (const float*)d_in[23];
    const float* db0  = (const float*)d_in[24];
    const float* dW1  = (const float*)d_in[25];
    const float* dU1  = (const float*)d_in[26];
    const float* db1  = (const float*)d_in[27];
    const float* fcW  = (const float*)d_in[28];
    const float* fcb  = (const float*)d_in[29];
    float* out = (float*)d_out;

    float *x0, *xpA, *xpB, *x1, *x2, *enc, *dh0, *comb, *hbuf, *cbuf, *cat;
    cudaGetSymbolAddress((void**)&x0,   g_x0);
    cudaGetSymbolAddress((void**)&xpA,  g_xpA);
    cudaGetSymbolAddress((void**)&xpB,  g_xpB);
    cudaGetSymbolAddress((void**)&x1,   g_x1);
    cudaGetSymbolAddress((void**)&x2,   g_x2);
    cudaGetSymbolAddress((void**)&enc,  g_enc);
    cudaGetSymbolAddress((void**)&dh0,  g_dh0);
    cudaGetSymbolAddress((void**)&comb, g_comb);
    cudaGetSymbolAddress((void**)&hbuf, g_hbuf);
    cudaGetSymbolAddress((void**)&cbuf, g_cbuf);
    cudaGetSymbolAddress((void**)&cat,  g_cat);

    cudaFuncSetAttribute(lstm_persist_kernel<8,2>,
                         cudaFuncAttributeMaxDynamicSharedMemorySize, 131072);
    cudaFuncSetAttribute(lstm_persist_kernel<4,1>,
                         cudaFuncAttributeMaxDynamicSharedMemorySize, 131072);

    // zero encoder initial states (dirs 0..3, both ping buffers + c)
    cudaMemsetAsync(hbuf, 0, (size_t)4 * 2 * BH * sizeof(float));
    cudaMemsetAsync(cbuf, 0, (size_t)4 * BH * sizeof(float));

    const int M = BB * SS;                      // 3072
    const dim3 gN2048(H4/128, M/128);           // (16, 24)
    const dim3 gN512 (HH/128, M/128);           // (4, 24)

    // ---- encoder ----
    embed_kernel<<<M, EE>>>(src_seq, src_emb, x0);
    sgemm_nt_bias<<<gN2048, 256>>>(x0, eW0f, eb0f, xpA, M, H4, EE);
    sgemm_nt_bias<<<gN2048, 256>>>(x0, eW0b, eb0b, xpB, M, H4, EE);

    {
        PDir pf = { xpA, eU0f, hbuf + (size_t)0*2*BH, cbuf + (size_t)0*BH, x1, 2*HH, 0,  0 };
        PDir pb = { xpB, eU0b, hbuf + (size_t)1*2*BH, cbuf + (size_t)1*BH, x1, 2*HH, HH, 1 };
        lstm_persist_kernel<8,2><<<128, 256, 131072>>>(pf, pb, SS, 128u);
    }

    sgemm_nt_bias<<<gN2048, 256>>>(x1, eW1f, eb1f, xpA, M, H4, 2*HH);
    sgemm_nt_bias<<<gN2048, 256>>>(x1, eW1b, eb1b, xpB, M, H4, 2*HH);

    {
        PDir pf = { xpA, eU1f, hbuf + (size_t)2*2*BH, cbuf + (size_t)2*BH, x2, 2*HH, 0,  0 };
        PDir pb = { xpB, eU1b, hbuf + (size_t)3*2*BH, cbuf + (size_t)3*BH, x2, 2*HH, HH, 1 };
        lstm_persist_kernel<8,2><<<128, 256, 131072>>>(pf, pb, SS, 128u);
    }

    sgemm_nt_bias<<<gN512, 256>>>(x2, out_W, out_b, enc, M, HH, 2*HH);

    // ---- bridge ----
    cat_states_kernel<<<(4*BB*2*HH + 255)/256, 256>>>();
    proj_kernel<<<64, 256>>>(cat + 0*BB*2*HH, hpW,                   hpb,      hbuf + (size_t)(4*2+0)*BH);
    proj_kernel<<<64, 256>>>(cat + 1*BB*2*HH, cpW,                   cpb,      cbuf + (size_t)4*BH);
    proj_kernel<<<64, 256>>>(cat + 2*BB*2*HH, hpW + (size_t)HH*2*HH, hpb + HH, hbuf + (size_t)(5*2+0)*BH);
    proj_kernel<<<64, 256>>>(cat + 3*BB*2*HH, cpW + (size_t)HH*2*HH, cpb + HH, cbuf + (size_t)5*BH);

    // ---- decoder layer 0 ----
    embed_kernel<<<M, EE>>>(trg_seq, trg_emb, x0);
    sgemm_nt_bias<<<gN2048, 256>>>(x0, dW0, db0, xpA, M, H4, EE);
    {
        PDir pd = { xpA, dU0, hbuf + (size_t)4*2*BH, cbuf + (size_t)4*BH, dh0, HH, 0, 0 };
        lstm_persist_kernel<4,1><<<128, 256, 131072>>>(pd, pd, TT, 128u);
    }

    // ---- decoder layer 1 (writes y into combined[:, 0:512]) ----
    sgemm_nt_bias<<<gN2048, 256>>>(dh0, dW1, db1, xpA, M, H4, HH);
    {
        PDir pd = { xpA, dU1, hbuf + (size_t)5*2*BH, cbuf + (size_t)5*BH, comb, 2*HH, 0, 0 };
        lstm_persist_kernel<4,1><<<128, 256, 131072>>>(pd, pd, TT, 128u);
    }

    // ---- attention (fills combined[:, 512:1024]) ----
    attn_kernel<<<M, 128>>>(src_seq);

    // ---- final FC: [3072,1024] x [1024,32000]^T + fcb ----
    sgemm_nt_bias<<<dim3(VV/128, M/128), 256>>>(comb, fcW, fcb, out, M, VV, 2*HH);
}